// round 17
// baseline (speedup 1.0000x reference)
#include <cuda_runtime.h>
#include <cuda_bf16.h>
#include <cuda_fp16.h>
#include <math.h>
#include <stdint.h>

#define NPTS 262144
#define CCH  256
#define KCLS 20
#define BN_TOT 288            // 256 h cols + 32 padded logit cols
#define NB_COLS 144           // N columns per CTA (2 N-tiles)

// ---------------- device globals ----------------
__device__ __half g_Bh[BN_TOT * CCH];              // B^T fp16 [n][k]
__device__ __half g_hb[(size_t)NPTS * CCH];        // h in fp16, 128 MB
__device__ float g_colsum[CCH];
__device__ float g_colsq[CCH];
__device__ float g_nll;
__device__ float g_vcnt;
__device__ float g_l1;
__device__ float g_cos;
__device__ float g_msum;

// ---------------- PTX helpers (plain-sm_103-safe) ----------------
__device__ __forceinline__ uint32_t smem_u32(const void* p) {
    uint32_t a;
    asm("{ .reg .u64 t; cvta.to.shared.u64 t, %1; cvt.u32.u64 %0, t; }" : "=r"(a) : "l"(p));
    return a;
}
__device__ __forceinline__ void sts64(uint32_t a, uint32_t x, uint32_t y) {
    asm volatile("st.shared.v2.b32 [%0], {%1,%2};" :: "r"(a), "r"(x), "r"(y));
}
__device__ __forceinline__ void cpa16(uint32_t dst, const void* src) {
    asm volatile("cp.async.cg.shared.global [%0], [%1], 16;" :: "r"(dst), "l"(src));
}
__device__ __forceinline__ void cpa_commit() {
    asm volatile("cp.async.commit_group;" ::: "memory");
}
__device__ __forceinline__ void ldm4(uint32_t* r, uint32_t a) {
    asm volatile("ldmatrix.sync.aligned.m8n8.x4.shared.b16 {%0,%1,%2,%3}, [%4];"
                 : "=r"(r[0]), "=r"(r[1]), "=r"(r[2]), "=r"(r[3]) : "r"(a));
}
__device__ __forceinline__ void ldm2(uint32_t* r, uint32_t a) {
    asm volatile("ldmatrix.sync.aligned.m8n8.x2.shared.b16 {%0,%1}, [%2];"
                 : "=r"(r[0]), "=r"(r[1]) : "r"(a));
}
__device__ __forceinline__ void mma_f16(float& d0, float& d1, float& d2, float& d3,
                                        uint32_t a0, uint32_t a1, uint32_t a2, uint32_t a3,
                                        uint32_t b0, uint32_t b1) {
    asm volatile("mma.sync.aligned.m16n8k16.row.col.f32.f16.f16.f32 "
                 "{%0,%1,%2,%3}, {%4,%5,%6,%7}, {%8,%9}, {%0,%1,%2,%3};"
                 : "+f"(d0), "+f"(d1), "+f"(d2), "+f"(d3)
                 : "r"(a0), "r"(a1), "r"(a2), "r"(a3), "r"(b0), "r"(b1));
}
__device__ __forceinline__ uint32_t pkh(__half a, __half b) {
    __half2 t = __halves2half2(a, b);
    return *(uint32_t*)&t;
}
__device__ __forceinline__ __half2 h2shfl_add(__half2 v, int o) {
    uint32_t u = *(uint32_t*)&v;
    uint32_t s = __shfl_xor_sync(0xffffffffu, u, o);
    return __hadd2(v, *(__half2*)&s);
}

// SMEM layout (bytes):
//   B resident: 144 rows x 528 B (132 words ≡ 4 mod 32 -> conflict-free ldmatrix)
//   A stages:   2 x (128 rows x 144 B)
#define B_STRIDE 528
#define SB_OFF   0
#define SB_SIZE  (144 * B_STRIDE)     // 76032
#define RSTRIDE  144
#define SA_OFF   SB_SIZE
#define ASTG     (128 * RSTRIDE)      // 18432
#define DYN_SMEM (SA_OFF + 2 * ASTG)  // 112896

// epilogue (floats), placed at dsm+0 (dead B region after post-loop barrier)
#define EP_B1  0
#define EP_BS  256
#define EP_SCS 288
#define EP_SCQ 544
#define EP_NV  800
#define EP_LG  832                    // 128*33 floats

// ---------------- kernel 1: build B^T fp16 + zero accumulators ----------------
__global__ void convw_kernel(const float* __restrict__ w1, const float* __restrict__ ws) {
    int n = blockIdx.x;    // 0..287 output channel
    int k = threadIdx.x;   // 0..255 input channel
    if (n == 0) {
        g_colsum[k] = 0.f;
        g_colsq[k]  = 0.f;
        if (k == 0) {
            g_nll = 0.f; g_vcnt = 0.f; g_l1 = 0.f; g_cos = 0.f; g_msum = 0.f;
        }
    }
    float v;
    if (n < 256)             v = w1[(size_t)k * 256 + n];
    else if (n - 256 < KCLS) v = ws[k * KCLS + (n - 256)];
    else                     v = 0.f;
    g_Bh[n * 256 + k] = __float2half_rn(v);
}

// ---------------- GEMM load helpers ----------------
__device__ __forceinline__ void a_issue(const float* __restrict__ feat,
                                        int rowBase, int k0, int tid, float4* va) {
#pragma unroll
    for (int t = 0; t < 8; t++) {
        int i = tid + t * 256;
        int r = i >> 4, s = i & 15;
        va[t] = *(const float4*)(feat + (size_t)(rowBase + r) * 256 + k0 + s * 4);
    }
}
__device__ __forceinline__ void a_store(uint32_t S, int tid, const float4* va) {
#pragma unroll
    for (int t = 0; t < 8; t++) {
        int i = tid + t * 256;
        int r = i >> 4, s = i & 15;
        uint32_t p0 = pkh(__float2half_rn(va[t].x), __float2half_rn(va[t].y));
        uint32_t p1 = pkh(__float2half_rn(va[t].z), __float2half_rn(va[t].w));
        sts64(S + (uint32_t)r * RSTRIDE + (uint32_t)s * 8, p0, p1);
    }
}
// full B load: 144 rows x 512 B = 4608 cpa16 (18/thread)
__device__ __forceinline__ void b_issue_all(int nbase, uint32_t sb, int tid) {
#pragma unroll
    for (int t = 0; t < 18; t++) {
        int i = tid + t * 256;
        int n = i >> 5, s = i & 31;
        cpa16(sb + SB_OFF + (uint32_t)n * B_STRIDE + (uint32_t)s * 16,
              g_Bh + (size_t)(nbase + n) * 256 + s * 8);
    }
}

// ---------------- kernel 2: fused GEMM (fp16 HMMA, B-resident, 2 CTA/SM) ----------------
__global__ __launch_bounds__(256, 2)
void gemm_kernel(const float* __restrict__ feat,
                 const float* __restrict__ b1v,
                 const float* __restrict__ bsv,
                 const int* __restrict__ segment) {
    extern __shared__ char dsm[];

    const int tid = threadIdx.x;
    const int wid = tid >> 5, lane = tid & 31;
    const int nb = blockIdx.x;                 // 0..1 N tile
    const int rowBase = blockIdx.y * 128;
    const int nbase = nb * NB_COLS;
    const int wm = wid & 3, wn = wid >> 2;     // 4m x 2n warps
    const int mwb = wm * 32;
    const int g = lane >> 2, tg = lane & 3;

    const uint32_t sb = smem_u32(dsm);

    float acc[2][9][4];
#pragma unroll
    for (int f = 0; f < 2; f++)
#pragma unroll
        for (int j = 0; j < 9; j++)
#pragma unroll
            for (int q = 0; q < 4; q++) acc[f][j][q] = 0.f;

    const uint32_t aOff = sb + SA_OFF + (uint32_t)(mwb + (lane & 15)) * RSTRIDE
                        + (uint32_t)(lane >> 4) * 16;
    const uint32_t bOff4 = sb + SB_OFF
        + (uint32_t)(wn * 72 + (lane & 7) + 8 * ((lane >> 4) & 1)) * B_STRIDE
        + (uint32_t)((lane >> 3) & 1) * 16;
    const uint32_t bOff2 = sb + SB_OFF
        + (uint32_t)(wn * 72 + 64 + (lane & 7)) * B_STRIDE
        + (uint32_t)((lane >> 3) & 1) * 16;

    // ---- prologue: B once + A(0), prefetch A(1) ----
    float4 regA[8];
    a_issue(feat, rowBase, 0, tid, regA);
    b_issue_all(nbase, sb, tid);
    cpa_commit();
    a_store(sb + SA_OFF, tid, regA);          // A(0) -> stage0
    a_issue(feat, rowBase, 64, tid, regA);    // prefetch A(1)
    asm volatile("cp.async.wait_group 0;" ::: "memory");   // B resident
    __syncthreads();

#pragma unroll 1
    for (int c = 0; c < 4; c++) {
        const uint32_t S = sb + SA_OFF + (uint32_t)((c & 1) * ASTG);
        const uint32_t kc = (uint32_t)(c * 128);
        // hidden A staging (stage (c+1)&1 freed by end-of-iter-(c-1) barrier)
        if (c < 3) a_store(sb + SA_OFF + (uint32_t)(((c + 1) & 1) * ASTG), tid, regA);
        if (c < 2) a_issue(feat, rowBase, (c + 2) * 64, tid, regA);

#pragma unroll
        for (int ks = 0; ks < 4; ks++) {
            const uint32_t ko = (uint32_t)ks * 32;
            uint32_t a0[4], a1[4];
            ldm4(a0, S + aOff - sb - SA_OFF + sb + SA_OFF + 0);  // placate nothing
            ldm4(a0, S + (aOff - (sb + SA_OFF)) + ko);
            ldm4(a1, S + (aOff - (sb + SA_OFF)) + 16 * RSTRIDE + ko);
#pragma unroll
            for (int jj = 0; jj < 4; jj++) {
                uint32_t b4[4];
                ldm4(b4, bOff4 + kc + ko + (uint32_t)jj * (16 * B_STRIDE));
                mma_f16(acc[0][2 * jj][0], acc[0][2 * jj][1], acc[0][2 * jj][2], acc[0][2 * jj][3],
                        a0[0], a0[1], a0[2], a0[3], b4[0], b4[1]);
                mma_f16(acc[1][2 * jj][0], acc[1][2 * jj][1], acc[1][2 * jj][2], acc[1][2 * jj][3],
                        a1[0], a1[1], a1[2], a1[3], b4[0], b4[1]);
                mma_f16(acc[0][2 * jj + 1][0], acc[0][2 * jj + 1][1], acc[0][2 * jj + 1][2], acc[0][2 * jj + 1][3],
                        a0[0], a0[1], a0[2], a0[3], b4[2], b4[3]);
                mma_f16(acc[1][2 * jj + 1][0], acc[1][2 * jj + 1][1], acc[1][2 * jj + 1][2], acc[1][2 * jj + 1][3],
                        a1[0], a1[1], a1[2], a1[3], b4[2], b4[3]);
            }
            uint32_t b2r[2];
            ldm2(b2r, bOff2 + kc + ko);
            mma_f16(acc[0][8][0], acc[0][8][1], acc[0][8][2], acc[0][8][3],
                    a0[0], a0[1], a0[2], a0[3], b2r[0], b2r[1]);
            mma_f16(acc[1][8][0], acc[1][8][1], acc[1][8][2], acc[1][8][3],
                    a1[0], a1[1], a1[2], a1[3], b2r[0], b2r[1]);
        }

        if (c < 3) __syncthreads();
    }

    // ---------------- epilogue (reuse dead B/A smem) ----------------
    __syncthreads();                          // all MMA reads done
    float* ep = (float*)dsm;
    if (tid < 256) { ep[EP_B1 + tid] = b1v[tid]; ep[EP_SCS + tid] = 0.f; ep[EP_SCQ + tid] = 0.f; }
    if (tid < 32)  ep[EP_BS + tid] = (tid < KCLS) ? bsv[tid] : 0.f;
    if (tid == 0)  { ep[EP_NV] = 0.f; ep[EP_NV + 1] = 0.f; }
    __syncthreads();

    uint32_t* hb32 = (uint32_t*)g_hb;
#pragma unroll
    for (int j = 0; j < 9; j++) {
        int gc = nbase + wn * 72 + j * 8 + tg * 2;
        if (gc < 256) {
            float bb0 = ep[EP_B1 + gc], bb1 = ep[EP_B1 + gc + 1];
            float cs0 = 0.f, cq0 = 0.f, cs1 = 0.f, cq1 = 0.f;
#pragma unroll
            for (int f = 0; f < 2; f++) {
                int r = rowBase + mwb + f * 16 + g;
                float v00 = acc[f][j][0] + bb0;
                float v01 = acc[f][j][1] + bb1;
                float v10 = acc[f][j][2] + bb0;
                float v11 = acc[f][j][3] + bb1;
                hb32[((size_t)r * 256 + gc) >> 1] =
                    pkh(__float2half_rn(v00), __float2half_rn(v01));
                hb32[((size_t)(r + 8) * 256 + gc) >> 1] =
                    pkh(__float2half_rn(v10), __float2half_rn(v11));
                cs0 += v00 + v10;  cq0 += v00 * v00 + v10 * v10;
                cs1 += v01 + v11;  cq1 += v01 * v01 + v11 * v11;
            }
#pragma unroll
            for (int o = 4; o <= 16; o <<= 1) {
                cs0 += __shfl_xor_sync(0xffffffffu, cs0, o);
                cq0 += __shfl_xor_sync(0xffffffffu, cq0, o);
                cs1 += __shfl_xor_sync(0xffffffffu, cs1, o);
                cq1 += __shfl_xor_sync(0xffffffffu, cq1, o);
            }
            if (g == 0) {
                atomicAdd(&ep[EP_SCS + gc], cs0);     atomicAdd(&ep[EP_SCQ + gc], cq0);
                atomicAdd(&ep[EP_SCS + gc + 1], cs1); atomicAdd(&ep[EP_SCQ + gc + 1], cq1);
            }
        } else {
            int lc = gc - 256;
            float bb0 = ep[EP_BS + lc], bb1 = ep[EP_BS + lc + 1];
#pragma unroll
            for (int f = 0; f < 2; f++) {
                int r = mwb + f * 16 + g;
                ep[EP_LG + r * 33 + lc]           = acc[f][j][0] + bb0;
                ep[EP_LG + r * 33 + lc + 1]       = acc[f][j][1] + bb1;
                ep[EP_LG + (r + 8) * 33 + lc]     = acc[f][j][2] + bb0;
                ep[EP_LG + (r + 8) * 33 + lc + 1] = acc[f][j][3] + bb1;
            }
        }
    }
    __syncthreads();

    if (nb == 1 && tid < 128) {
        int row = tid;
        float m = -1e30f;
        float lg[KCLS];
#pragma unroll
        for (int q = 0; q < KCLS; q++) { lg[q] = ep[EP_LG + row * 33 + q]; m = fmaxf(m, lg[q]); }
        float se = 0.f;
#pragma unroll
        for (int q = 0; q < KCLS; q++) se += expf(lg[q] - m);
        int t = segment[rowBase + row];
        bool valid = (t != -1);
        float picked = ep[EP_LG + row * 33 + (valid ? t : 0)];
        float vf = valid ? 1.f : 0.f;
        float nll = (m + logf(se) - picked) * vf;
#pragma unroll
        for (int o = 16; o > 0; o >>= 1) {
            nll += __shfl_xor_sync(0xffffffffu, nll, o);
            vf  += __shfl_xor_sync(0xffffffffu, vf, o);
        }
        if (lane == 0) { atomicAdd(&ep[EP_NV], nll); atomicAdd(&ep[EP_NV + 1], vf); }
    }
    {
        int lo = nb * NB_COLS;
        int hi = nb ? 256 : NB_COLS;
        for (int i = lo + tid; i < hi; i += 256) {
            atomicAdd(&g_colsum[i], ep[EP_SCS + i]);
            atomicAdd(&g_colsq[i], ep[EP_SCQ + i]);
        }
    }
    __syncthreads();
    if (nb == 1 && tid == 0) { atomicAdd(&g_nll, ep[EP_NV]); atomicAdd(&g_vcnt, ep[EP_NV + 1]); }
}

// ---------------- kernel 3: bias v5 — 16 lanes/point, half2, params in regs ----------------
__global__ __launch_bounds__(256, 3)
void bias_kernel(const float* __restrict__ coord,
                 const float* __restrict__ centroid,
                 const int* __restrict__ instance,
                 const float* __restrict__ gamma,
                 const float* __restrict__ beta,
                 const float* __restrict__ w2,
                 const float* __restrict__ b2) {
    __shared__ float red[8][3];

    const int tid = threadIdx.x;
    const int warp = tid >> 5, lane = tid & 31;
    const int l16 = lane & 15, half = lane >> 4;
    const int c0 = l16 * 16;                    // this lane's 16 channels

    // per-lane BN-affine + w2 params (packed half2, registers)
    __half2 pa[8], psc[8], pw0[8], pw1[8], pw2[8];
    const float invN = 1.0f / (float)NPTS;
#pragma unroll
    for (int u = 0; u < 8; u++) {
        int cA = c0 + 2 * u, cB = cA + 1;
        float muA = g_colsum[cA] * invN, muB = g_colsum[cB] * invN;
        float aA = gamma[cA] * rsqrtf(g_colsq[cA] * invN - muA * muA + 1e-3f);
        float aB = gamma[cB] * rsqrtf(g_colsq[cB] * invN - muB * muB + 1e-3f);
        pa[u]  = __floats2half2_rn(aA, aB);
        psc[u] = __floats2half2_rn(beta[cA] - muA * aA, beta[cB] - muB * aB);
        pw0[u] = __floats2half2_rn(w2[cA * 3 + 0], w2[cB * 3 + 0]);
        pw1[u] = __floats2half2_rn(w2[cA * 3 + 1], w2[cB * 3 + 1]);
        pw2[u] = __floats2half2_rn(w2[cA * 3 + 2], w2[cB * 3 + 2]);
    }
    const float b2x = b2[0], b2y = b2[1], b2z = b2[2];
    const __half2 hzero = __float2half2_rn(0.f);

    float l1acc = 0.f, cosacc = 0.f, mcount = 0.f;
    const int base = (blockIdx.x * 8 + warp) * 32;

#pragma unroll 2
    for (int it = 0; it < 8; it++) {
        int n0 = base + it * 4 + half * 2;       // this half-warp's 2 points
        __half2 d[2][3];
#pragma unroll
        for (int q = 0; q < 2; q++) {
            const uint4* hp = (const uint4*)(g_hb + (size_t)(n0 + q) * 256 + c0);
            uint4 hv0 = hp[0];
            uint4 hv1 = hp[1];
            __half2 v0 = __hmax2(__hfma2(*(__half2*)&hv0.x, pa[0], psc[0]), hzero);
            __half2 v1 = __hmax2(__hfma2(*(__half2*)&hv0.y, pa[1], psc[1]), hzero);
            __half2 v2 = __hmax2(__hfma2(*(__half2*)&hv0.z, pa[2], psc[2]), hzero);
            __half2 v3 = __hmax2(__hfma2(*(__half2*)&hv0.w, pa[3], psc[3]), hzero);
            __half2 v4 = __hmax2(__hfma2(*(__half2*)&hv1.x, pa[4], psc[4]), hzero);
            __half2 v5 = __hmax2(__hfma2(*(__half2*)&hv1.y, pa[5], psc[5]), hzero);
            __half2 v6 = __hmax2(__hfma2(*(__half2*)&hv1.z, pa[6], psc[6]), hzero);
            __half2 v7 = __hmax2(__hfma2(*(__half2*)&hv1.w, pa[7], psc[7]), hzero);
            d[q][0] = __hfma2(v7, pw0[7], __hfma2(v6, pw0[6], __hfma2(v5, pw0[5],
                      __hfma2(v4, pw0[4], __hfma2(v3, pw0[3], __hfma2(v2, pw0[2],
                      __hfma2(v1, pw0[1], __hmul2(v0, pw0[0]))))))));
            d[q][1] = __hfma2(v7, pw1[7], __hfma2(v6, pw1[6], __hfma2(v5, pw1[5],
                      __hfma2(v4, pw1[4], __hfma2(v3, pw1[3], __hfma2(v2, pw1[2],
                      __hfma2(v1, pw1[1], __hmul2(v0, pw1[0]))))))));
            d[q][2] = __hfma2(v7, pw2[7], __hfma2(v6, pw2[6], __hfma2(v5, pw2[5],
                      __hfma2(v4, pw2[4], __hfma2(v3, pw2[3], __hfma2(v2, pw2[2],
                      __hfma2(v1, pw2[1], __hmul2(v0, pw2[0]))))))));
        }
        // 6 packed butterflies over the 16-lane half-warp (offsets 1..8)
#pragma unroll
        for (int o = 1; o <= 8; o <<= 1) {
#pragma unroll
            for (int q = 0; q < 2; q++) {
                d[q][0] = h2shfl_add(d[q][0], o);
                d[q][1] = h2shfl_add(d[q][1], o);
                d[q][2] = h2shfl_add(d[q][2], o);
            }
        }
        if (l16 < 2) {                            // lanes 0,1,16,17 finish 4 points in parallel
            int q = l16;
            int n = n0 + q;
            float2 f0 = __half22float2(d[q][0]);
            float2 f1 = __half22float2(d[q][1]);
            float2 f2 = __half22float2(d[q][2]);
            float px = f0.x + f0.y + b2x;
            float py = f1.x + f1.y + b2y;
            float pz = f2.x + f2.y + b2z;
            float gx = centroid[3 * n + 0] - coord[3 * n + 0];
            float gy = centroid[3 * n + 1] - coord[3 * n + 1];
            float gz = centroid[3 * n + 2] - coord[3 * n + 2];
            float mask = (instance[n] != -1) ? 1.f : 0.f;
            float l1 = fabsf(px - gx) + fabsf(py - gy) + fabsf(pz - gz);
            float pn = sqrtf(px * px + py * py + pz * pz) + 1e-8f;
            float gn = sqrtf(gx * gx + gy * gy + gz * gz) + 1e-8f;
            float cs = -(px * gx + py * gy + pz * gz) / (pn * gn);
            l1acc  += l1 * mask;
            cosacc += cs * mask;
            mcount += mask;
        }
    }
    // combine lanes 0,1,16,17 (others hold zeros)
    l1acc  += __shfl_xor_sync(0xffffffffu, l1acc, 1);
    cosacc += __shfl_xor_sync(0xffffffffu, cosacc, 1);
    mcount += __shfl_xor_sync(0xffffffffu, mcount, 1);
    l1acc  += __shfl_xor_sync(0xffffffffu, l1acc, 16);
    cosacc += __shfl_xor_sync(0xffffffffu, cosacc, 16);
    mcount += __shfl_xor_sync(0xffffffffu, mcount, 16);
    if (lane == 0) {
        red[warp][0] = l1acc;
        red[warp][1] = cosacc;
        red[warp][2] = mcount;
    }
    __syncthreads();
    if (tid == 0) {
        float s0 = 0.f, s1 = 0.f, s2 = 0.f;
        for (int w = 0; w < 8; w++) { s0 += red[w][0]; s1 += red[w][1]; s2 += red[w][2]; }
        atomicAdd(&g_l1, s0);
        atomicAdd(&g_cos, s1);
        atomicAdd(&g_msum, s2);
    }
}

// ---------------- kernel 4: finalize ----------------
__global__ void final_kernel(float* __restrict__ out) {
    float seg_loss = g_nll / (g_vcnt + 1e-8f);
    float l1_loss  = g_l1  / (g_msum + 1e-8f);
    float cos_loss = g_cos / (g_msum + 1e-8f);
    out[0] = seg_loss + l1_loss + cos_loss;
    out[1] = seg_loss;
    out[2] = l1_loss;
    out[3] = cos_loss;
}

// ---------------- launcher ----------------
extern "C" void kernel_launch(void* const* d_in, const int* in_sizes, int n_in,
                              void* d_out, int out_size) {
    const float* feat     = (const float*)d_in[0];
    const float* coord    = (const float*)d_in[1];
    const float* centroid = (const float*)d_in[2];
    const int*   segment  = (const int*)d_in[3];
    const int*   instance = (const int*)d_in[4];
    const float* w1       = (const float*)d_in[5];
    const float* b1       = (const float*)d_in[6];
    const float* gamma    = (const float*)d_in[7];
    const float* beta     = (const float*)d_in[8];
    const float* w2       = (const float*)d_in[9];
    const float* b2       = (const float*)d_in[10];
    const float* ws       = (const float*)d_in[11];
    const float* bs       = (const float*)d_in[12];
    float* out = (float*)d_out;

    static int smem_set = 0;
    if (!smem_set) {
        cudaFuncSetAttribute(gemm_kernel, cudaFuncAttributeMaxDynamicSharedMemorySize, DYN_SMEM);
        smem_set = 1;
    }

    convw_kernel<<<BN_TOT, 256>>>(w1, ws);
    gemm_kernel<<<dim3(2, NPTS / 128), 256, DYN_SMEM>>>(feat, b1, bs, segment);
    bias_kernel<<<NPTS / 256, 256>>>(coord, centroid, instance, gamma, beta, w2, b2);
    final_kernel<<<1, 1>>>(out);
}